// round 14
// baseline (speedup 1.0000x reference)
#include <cuda_runtime.h>
#include <cuda_fp16.h>
#include <math.h>
#include <stdint.h>

#define BATCH 4096
#define DIM   1024
#define TEMB  256
#define NL    4
#define D2    ((size_t)DIM * DIM)

#define EP_BIAS  0
#define EP_ADD   1
#define EP_GELUH 3
#define EP_HALF  4

__device__ float g_h  [BATCH * DIM];
__device__ float g_bp [NL * DIM];
__device__ float g_zero[16 * DIM];
__device__ __half g_adah[(size_t)BATCH * 16 * DIM];
__device__ __half g_xh [BATCH * DIM];
__device__ __half g_y  [BATCH * DIM];
__device__ __half g_st [BATCH * TEMB];
__device__ __half g_big[BATCH * 4 * DIM];
__device__ __half g_woh[NL * D2];
__device__ __half g_wvt[NL * D2];
__device__ __half g_wp [NL * D2];
#define WTOT (38 * D2)
__device__ __half g_w[WTOT];

__device__ __forceinline__ uint32_t smem_u32(const void* p) {
    uint32_t a;
    asm("{ .reg .u64 t; cvta.to.shared.u64 t, %1; cvt.u32.u64 %0, t; }" : "=r"(a) : "l"(p));
    return a;
}
__device__ __forceinline__ void ldsm4(uint32_t* r, uint32_t a) {
    asm volatile("ldmatrix.sync.aligned.m8n8.x4.shared.b16 {%0,%1,%2,%3}, [%4];"
                 : "=r"(r[0]), "=r"(r[1]), "=r"(r[2]), "=r"(r[3]) : "r"(a));
}
__device__ __forceinline__ void mma16816(float* c, const uint32_t* a, const uint32_t* b) {
    asm volatile("mma.sync.aligned.m16n8k16.row.col.f32.f16.f16.f32 "
                 "{%0,%1,%2,%3}, {%4,%5,%6,%7}, {%8,%9}, {%0,%1,%2,%3};"
                 : "+f"(c[0]), "+f"(c[1]), "+f"(c[2]), "+f"(c[3])
                 : "r"(a[0]), "r"(a[1]), "r"(a[2]), "r"(a[3]), "r"(b[0]), "r"(b[1]));
}
__device__ __forceinline__ uint32_t pack2(__half a, __half b) {
    return (uint32_t)__half_as_ushort(a) | ((uint32_t)__half_as_ushort(b) << 16);
}
__device__ __forceinline__ float gelu1(float v) {
    return 0.5f * v * (1.f + erff(v * 0.70710678118654752f));
}

// ---- GEMM: C[M,N] = A[M,K] @ W[N,K]^T, fp16 in, fp32 accum ----
// Templated on NT (warp n8-tile count): NT=8 -> BN=256, NT=4 -> BN=128.
#define BM 128
#define NSTAGE 4
#define NTHR 512
#define SMEM8 (NSTAGE * (16384 + 256 * 128))   // 196608
#define SMEM4 (NSTAGE * (16384 + 128 * 128))   // 131072

__device__ __forceinline__ void ld_tile(uint32_t tb, const __half* __restrict__ g,
                                        int row0, int K, int k0, int nrows, int tid) {
    const char* base = (const char*)(g + (size_t)row0 * K + k0);
    const size_t rs = (size_t)K * 2;
    #pragma unroll
    for (int i = tid; i < nrows * 8; i += NTHR) {
        int r = i >> 3, c2 = i & 7;
        uint32_t off = (uint32_t)(r * 128 + c2 * 16);
        uint32_t dst = tb + (off ^ ((off >> 3) & 0x70));
        asm volatile("cp.async.cg.shared.global [%0], [%1], 16;"
                     :: "r"(dst), "l"(base + (size_t)r * rs + c2 * 16));
    }
}

template<int EP, int NT>
__global__ void __launch_bounds__(NTHR, 1)
gemm_tc(const __half* __restrict__ A, const __half* __restrict__ W,
        const float* __restrict__ bias, const float* __restrict__ extra,
        float* __restrict__ Cf, __half* __restrict__ Oh,
        int N, int K, size_t zA, size_t zW, size_t zC)
{
    constexpr int BNv  = NT * 32;
    constexpr int STGv = 16384 + BNv * 128;
    extern __shared__ __align__(1024) char smem[];
    uint32_t sb = smem_u32(smem);
    const int tid = threadIdx.x, lane = tid & 31, wid = tid >> 5;
    const int bm = blockIdx.y * BM, bn = blockIdx.x * BNv;
    const size_t z = blockIdx.z;
    A += z * zA; W += z * zW;

    float acc[2][NT][4] = {};

    const int wm = (wid & 3) * 32, wn = (wid >> 2) * (NT * 8);
    const int arow = (lane & 7) + ((lane >> 3) & 1) * 8;
    const int ac   = (lane >> 4) & 1;
    const uint32_t axor = (uint32_t)((arow & 7) << 4);
    uint32_t aterm[2];
    #pragma unroll
    for (int mt = 0; mt < 2; mt++) aterm[mt] = (uint32_t)((wm + mt * 16 + arow) * 128);

    const int brow = lane & 7;
    const int bk   = (lane >> 3) & 1;
    const int bn8  = (lane >> 4) & 1;
    const uint32_t bxor = (uint32_t)(brow << 4);
    uint32_t bterm[NT / 2];
    #pragma unroll
    for (int ntp = 0; ntp < NT / 2; ntp++)
        bterm[ntp] = (uint32_t)((wn + ntp * 16 + bn8 * 8 + brow) * 128);

    auto stage = [&](int s, int c) {
        uint32_t st = sb + (uint32_t)s * STGv;
        ld_tile(st,         A, bm, K, c * 64, 128, tid);
        ld_tile(st + 16384, W, bn, K, c * 64, BNv, tid);
        asm volatile("cp.async.commit_group;" ::: "memory");
    };

    const int nch = K >> 6;
    stage(0, 0); stage(1, 1); stage(2, 2);

    for (int c = 0; c < nch; c++) {
        asm volatile("cp.async.wait_group 2;" ::: "memory");
        __syncthreads();
        if (c + 3 < nch) stage((c + 3) % NSTAGE, c + 3);
        else             asm volatile("cp.async.commit_group;" ::: "memory");

        uint32_t st = sb + (uint32_t)(c % NSTAGE) * STGv;
        #pragma unroll
        for (int ks = 0; ks < 4; ks++) {
            const uint32_t ka = (uint32_t)(ks * 32 + ac * 16);
            const uint32_t kb = (uint32_t)(ks * 32 + bk * 16);
            uint32_t fb[NT][2];
            #pragma unroll
            for (int ntp = 0; ntp < NT / 2; ntp++)
                ldsm4(&fb[2 * ntp][0], st + 16384 + bterm[ntp] + (kb ^ bxor));
            #pragma unroll
            for (int mt = 0; mt < 2; mt++) {
                uint32_t fa[4];
                ldsm4(fa, st + aterm[mt] + (ka ^ axor));
                #pragma unroll
                for (int nt = 0; nt < NT; nt++)
                    mma16816(acc[mt][nt], fa, fb[nt]);
            }
        }
    }

    const int r0b = bm + wm + (lane >> 2);
    const int c0b = bn + wn + 2 * (lane & 3);
    #pragma unroll
    for (int mt = 0; mt < 2; mt++) {
        const int row0 = r0b + mt * 16, row1 = row0 + 8;
        #pragma unroll
        for (int nt = 0; nt < NT; nt++) {
            const int col = c0b + nt * 8;
            const float b0 = bias[col], b1 = bias[col + 1];
            float v00 = acc[mt][nt][0] + b0, v01 = acc[mt][nt][1] + b1;
            float v10 = acc[mt][nt][2] + b0, v11 = acc[mt][nt][3] + b1;
            const size_t g0 = z * zC + (size_t)row0 * N + col;
            const size_t g1 = z * zC + (size_t)row1 * N + col;

            if (EP == EP_GELUH) {
                v00 = gelu1(v00); v01 = gelu1(v01); v10 = gelu1(v10); v11 = gelu1(v11);
            }
            if (EP == EP_GELUH || EP == EP_HALF) {
                *(uint32_t*)(Oh + g0) = pack2(__float2half_rn(v00), __float2half_rn(v01));
                *(uint32_t*)(Oh + g1) = pack2(__float2half_rn(v10), __float2half_rn(v11));
            } else if (EP == EP_ADD) {
                float2 e0 = *(const float2*)(extra + g0);
                float2 e1 = *(const float2*)(extra + g1);
                *(float2*)(Cf + g0) = make_float2(v00 + e0.x, v01 + e0.y);
                *(float2*)(Cf + g1) = make_float2(v10 + e1.x, v11 + e1.y);
            } else {
                *(float2*)(Cf + g0) = make_float2(v00, v01);
                *(float2*)(Cf + g1) = make_float2(v10, v11);
            }
        }
    }
}

// ---- elementwise / small kernels ----
template<int SILU>
__global__ void cvt_k(const float* __restrict__ s, __half* __restrict__ o, int n) {
    int i = (blockIdx.x * blockDim.x + threadIdx.x) * 8;
    if (i >= n) return;
    float4 a = *(const float4*)(s + i);
    float4 b = *(const float4*)(s + i + 4);
    if (SILU) {
        a.x /= (1.f + expf(-a.x)); a.y /= (1.f + expf(-a.y));
        a.z /= (1.f + expf(-a.z)); a.w /= (1.f + expf(-a.w));
        b.x /= (1.f + expf(-b.x)); b.y /= (1.f + expf(-b.y));
        b.z /= (1.f + expf(-b.z)); b.w /= (1.f + expf(-b.w));
    }
    uint4 r;
    r.x = pack2(__float2half_rn(a.x), __float2half_rn(a.y));
    r.y = pack2(__float2half_rn(a.z), __float2half_rn(a.w));
    r.z = pack2(__float2half_rn(b.x), __float2half_rn(b.y));
    r.w = pack2(__float2half_rn(b.z), __float2half_rn(b.w));
    *(uint4*)(o + i) = r;
}

__global__ void transpose_wv(const float* __restrict__ wqkv, __half* __restrict__ wvt) {
    __shared__ float tile[32][33];
    const int l = blockIdx.z;
    const float* src = wqkv + (size_t)l * 3 * D2 + 2 * D2;
    __half* dst = wvt + (size_t)l * D2;
    const int k0 = blockIdx.x * 32, m0 = blockIdx.y * 32;
    const int tx = threadIdx.x, ty = threadIdx.y;
    #pragma unroll
    for (int i = 0; i < 4; i++) {
        int r = ty + i * 8;
        tile[r][tx] = src[(size_t)(m0 + r) * DIM + k0 + tx];
    }
    __syncthreads();
    #pragma unroll
    for (int i = 0; i < 4; i++) {
        int r = ty + i * 8;
        dst[(size_t)(k0 + r) * DIM + m0 + tx] = __float2half_rn(tile[tx][r]);
    }
}

__global__ __launch_bounds__(256) void bprime_k(
    const float* __restrict__ wo, const float* __restrict__ bqkv,
    const float* __restrict__ bo, float* __restrict__ bp)
{
    const int n = blockIdx.x, l = blockIdx.y, t = threadIdx.x;
    const float* wr = wo + (size_t)l * D2 + (size_t)n * DIM;
    const float* bv = bqkv + (size_t)l * 3 * DIM + 2 * DIM;
    float s = 0.f;
    for (int k = t; k < DIM; k += 256) s += wr[k] * bv[k];
    #pragma unroll
    for (int o = 16; o; o >>= 1) s += __shfl_xor_sync(0xffffffffu, s, o);
    __shared__ float ss[8];
    if ((t & 31) == 0) ss[t >> 5] = s;
    __syncthreads();
    if (t == 0) {
        float r = 0.f;
        #pragma unroll
        for (int i = 0; i < 8; i++) r += ss[i];
        bp[l * DIM + n] = r + bo[l * DIM + n];
    }
}

__device__ __forceinline__ void ln_apply(
    float4* v, int row, int lane,
    const float* __restrict__ g, const float* __restrict__ b,
    const __half* __restrict__ ada, int so, int sho, __half* __restrict__ oh)
{
    float s = 0.f, q = 0.f;
    #pragma unroll
    for (int i = 0; i < 8; i++) {
        s += v[i].x + v[i].y + v[i].z + v[i].w;
        q += v[i].x*v[i].x + v[i].y*v[i].y + v[i].z*v[i].z + v[i].w*v[i].w;
    }
    #pragma unroll
    for (int o = 16; o; o >>= 1) {
        s += __shfl_xor_sync(0xffffffffu, s, o);
        q += __shfl_xor_sync(0xffffffffu, q, o);
    }
    const float m   = s * (1.f / DIM);
    const float inv = rsqrtf(q * (1.f / DIM) - m * m + 1e-5f);
    const __half* ar = ada ? ada + (size_t)row * (16 * DIM) : nullptr;
    #pragma unroll
    for (int i = 0; i < 8; i++) {
        const int e = (i * 32 + lane) * 4;
        float4 g4 = ((const float4*)g)[i * 32 + lane];
        float4 b4 = ((const float4*)b)[i * 32 + lane];
        float o0 = (v[i].x - m) * inv * g4.x + b4.x;
        float o1 = (v[i].y - m) * inv * g4.y + b4.y;
        float o2 = (v[i].z - m) * inv * g4.z + b4.z;
        float o3 = (v[i].w - m) * inv * g4.w + b4.w;
        if (ar) {
            __half2 sa = ((const __half2*)(ar + so + e))[0];
            __half2 sb2 = ((const __half2*)(ar + so + e))[1];
            __half2 ha = ((const __half2*)(ar + sho + e))[0];
            __half2 hb = ((const __half2*)(ar + sho + e))[1];
            o0 = o0 * (1.f + __low2float(sa))  + __low2float(ha);
            o1 = o1 * (1.f + __high2float(sa)) + __high2float(ha);
            o2 = o2 * (1.f + __low2float(sb2)) + __low2float(hb);
            o3 = o3 * (1.f + __high2float(sb2))+ __high2float(hb);
        }
        ((uint2*)(oh + (size_t)row * DIM))[i * 32 + lane] =
            make_uint2(pack2(__float2half_rn(o0), __float2half_rn(o1)),
                       pack2(__float2half_rn(o2), __float2half_rn(o3)));
    }
}

__global__ __launch_bounds__(256) void ln_half_k(
    const float* __restrict__ h, const float* __restrict__ g,
    const float* __restrict__ b, const __half* __restrict__ ada,
    int so, int sho, __half* __restrict__ oh)
{
    const int lane = threadIdx.x & 31;
    const int row  = blockIdx.x * 8 + (threadIdx.x >> 5);
    const float4* hr = (const float4*)(h + (size_t)row * DIM);
    float4 v[8];
    #pragma unroll
    for (int i = 0; i < 8; i++) v[i] = hr[i * 32 + lane];
    ln_apply(v, row, lane, g, b, ada, so, sho, oh);
}

__global__ __launch_bounds__(256) void ln_res_k(
    float* __restrict__ h, const __half* __restrict__ y,
    const float* __restrict__ g, const float* __restrict__ b,
    const __half* __restrict__ ada, int so, int sho, __half* __restrict__ oh)
{
    const int lane = threadIdx.x & 31;
    const int row  = blockIdx.x * 8 + (threadIdx.x >> 5);
    float4* hr = (float4*)(h + (size_t)row * DIM);
    const uint2* yr = (const uint2*)(y + (size_t)row * DIM);
    float4 v[8];
    #pragma unroll
    for (int i = 0; i < 8; i++) {
        float4 t = hr[i * 32 + lane];
        uint2 yv = yr[i * 32 + lane];
        __half2 y0 = *(__half2*)&yv.x, y1 = *(__half2*)&yv.y;
        t.x += __low2float(y0); t.y += __high2float(y0);
        t.z += __low2float(y1); t.w += __high2float(y1);
        hr[i * 32 + lane] = t;
        v[i] = t;
    }
    ln_apply(v, row, lane, g, b, ada, so, sho, oh);
}

// ---- launch ----
extern "C" void kernel_launch(void* const* d_in, const int* in_sizes, int n_in,
                              void* d_out, int out_size)
{
    const float* x        = (const float*)d_in[0];
    const float* t_emb    = (const float*)d_in[1];
    const float* condition= (const float*)d_in[2];
    const float* in_w     = (const float*)d_in[3];
    const float* in_b     = (const float*)d_in[4];
    const float* ln1_g    = (const float*)d_in[5];
    const float* ln1_b    = (const float*)d_in[6];
    const float* wqkv     = (const float*)d_in[7];
    const float* bqkv     = (const float*)d_in[8];
    const float* wo       = (const float*)d_in[9];
    const float* bo       = (const float*)d_in[10];
    const float* ln2_g    = (const float*)d_in[11];
    const float* ln2_b    = (const float*)d_in[12];
    const float* w1       = (const float*)d_in[13];
    const float* b1       = (const float*)d_in[14];
    const float* w2       = (const float*)d_in[15];
    const float* b2       = (const float*)d_in[16];
    const float* ada_w    = (const float*)d_in[17];
    const float* ada_b    = (const float*)d_in[18];
    const float* out_ln_g = (const float*)d_in[19];
    const float* out_ln_b = (const float*)d_in[20];
    const float* out_w    = (const float*)d_in[21];
    const float* out_b    = (const float*)d_in[22];

    float *h, *bp, *zero;
    __half *adah,*xh,*y,*st,*big,*w,*woh,*wvt,*wp;
    cudaGetSymbolAddress((void**)&h,    g_h);
    cudaGetSymbolAddress((void**)&bp,   g_bp);
    cudaGetSymbolAddress((void**)&zero, g_zero);
    cudaGetSymbolAddress((void**)&adah, g_adah);
    cudaGetSymbolAddress((void**)&xh,   g_xh);
    cudaGetSymbolAddress((void**)&y,    g_y);
    cudaGetSymbolAddress((void**)&st,   g_st);
    cudaGetSymbolAddress((void**)&big,  g_big);
    cudaGetSymbolAddress((void**)&w,    g_w);
    cudaGetSymbolAddress((void**)&woh,  g_woh);
    cudaGetSymbolAddress((void**)&wvt,  g_wvt);
    cudaGetSymbolAddress((void**)&wp,   g_wp);

    cudaFuncSetAttribute(gemm_tc<EP_BIAS,8>,  cudaFuncAttributeMaxDynamicSharedMemorySize, SMEM8);
    cudaFuncSetAttribute(gemm_tc<EP_ADD,8>,   cudaFuncAttributeMaxDynamicSharedMemorySize, SMEM8);
    cudaFuncSetAttribute(gemm_tc<EP_HALF,8>,  cudaFuncAttributeMaxDynamicSharedMemorySize, SMEM8);
    cudaFuncSetAttribute(gemm_tc<EP_GELUH,4>, cudaFuncAttributeMaxDynamicSharedMemorySize, SMEM4);

    const size_t OFF_ADA = D2, OFF_W1 = 5 * D2, OFF_W2 = 21 * D2, OFF_OUT = 37 * D2;

    const int sb = 256;
    auto cvtS = [&](cudaStream_t sN, const float* src, __half* o, size_t n) {
        cvt_k<0><<<(int)((n / 8 + sb - 1) / sb), sb, 0, sN>>>(src, o, (int)n);
    };

    const dim3 blk(NTHR);
    const dim3 gD   (DIM / 256, BATCH / BM);          // (4, 32)   NT=8
    const dim3 gW1  (4 * DIM / 128, BATCH / BM);      // (32, 32)  NT=4 -> 1024 CTAs
    const dim3 gAda (16 * DIM / 256, BATCH / BM);     // (64, 32)  NT=8
    const dim3 gWp  (DIM / 256, DIM / BM, NL);        // (4, 8, 4) NT=8

    // fork: big weight conversions overlap head GEMMs
    cudaStream_t s2;
    cudaStreamCreateWithFlags(&s2, cudaStreamNonBlocking);
    cudaEvent_t eF, eJ;
    cudaEventCreateWithFlags(&eF, cudaEventDisableTiming);
    cudaEventCreateWithFlags(&eJ, cudaEventDisableTiming);
    cudaEventRecord(eF, 0);
    cudaStreamWaitEvent(s2, eF, 0);
    cvtS(s2, w1,    w + OFF_W1,  16 * D2);
    cvtS(s2, w2,    w + OFF_W2,  16 * D2);
    cvtS(s2, out_w, w + OFF_OUT, D2);
    cudaEventRecord(eJ, s2);

    cvtS(0, x, xh, (size_t)BATCH * DIM);
    cvt_k<1><<<(BATCH * TEMB / 8 + sb - 1) / sb, sb>>>(t_emb, st, BATCH * TEMB);
    cvtS(0, in_w,  w,           D2);
    cvtS(0, ada_w, w + OFF_ADA, 4 * D2);
    cvtS(0, wo,    woh,         4 * D2);
    transpose_wv<<<dim3(32, 32, NL), dim3(32, 8)>>>(wqkv, wvt);
    bprime_k<<<dim3(DIM, NL), 256>>>(wo, bqkv, bo, bp);

    gemm_tc<EP_HALF,8><<<gWp, blk, SMEM8>>>(woh, wvt, zero, nullptr, nullptr, wp,
                                            DIM, DIM, D2, D2, D2);
    gemm_tc<EP_HALF,8><<<gAda, blk, SMEM8>>>(st, w + OFF_ADA, ada_b, nullptr, nullptr, adah,
                                             16 * DIM, TEMB, 0, 0, 0);
    gemm_tc<EP_ADD,8><<<gD, blk, SMEM8>>>(xh, w, in_b, condition, h, nullptr,
                                          DIM, DIM, 0, 0, 0);
    ln_half_k<<<BATCH / 8, 256>>>(h, ln1_g, ln1_b, adah, 0, DIM, xh);

    cudaStreamWaitEvent(0, eJ, 0);

    for (int l = 0; l < NL; l++) {
        const int ao = l * 4 * DIM;
        gemm_tc<EP_HALF,8><<<gD, blk, SMEM8>>>(xh, wp + (size_t)l * D2,
                                               bp + (size_t)l * DIM, nullptr, nullptr, y,
                                               DIM, DIM, 0, 0, 0);
        ln_res_k<<<BATCH / 8, 256>>>(h, y, ln2_g + (size_t)l * DIM, ln2_b + (size_t)l * DIM,
                                     adah, ao + 2 * DIM, ao + 3 * DIM, xh);
        // w1 GEMM: BN=128 tiles -> 1024 CTAs -> 98.8% wave efficiency
        gemm_tc<EP_GELUH,4><<<gW1, blk, SMEM4>>>(xh, w + OFF_W1 + (size_t)l * 4 * D2,
                                                 b1 + (size_t)l * 4 * DIM, nullptr, nullptr, big,
                                                 4 * DIM, DIM, 0, 0, 0);
        gemm_tc<EP_HALF,8><<<gD, blk, SMEM8>>>(big, w + OFF_W2 + (size_t)l * 4 * D2,
                                               b2 + (size_t)l * DIM, nullptr, nullptr, y,
                                               DIM, 4 * DIM, 0, 0, 0);
        if (l < NL - 1) {
            const int ao2 = (l + 1) * 4 * DIM;
            ln_res_k<<<BATCH / 8, 256>>>(h, y, ln1_g + (size_t)(l + 1) * DIM,
                                         ln1_b + (size_t)(l + 1) * DIM,
                                         adah, ao2, ao2 + DIM, xh);
        } else {
            ln_res_k<<<BATCH / 8, 256>>>(h, y, out_ln_g, out_ln_b, nullptr, 0, 0, xh);
        }
    }

    gemm_tc<EP_BIAS,8><<<gD, blk, SMEM8>>>(xh, w + OFF_OUT, out_b, nullptr,
                                           (float*)d_out, nullptr, DIM, DIM, 0, 0, 0);
}

// round 15
// speedup vs baseline: 1.0030x; 1.0030x over previous
#include <cuda_runtime.h>
#include <cuda_fp16.h>
#include <math.h>
#include <stdint.h>

#define BATCH 4096
#define DIM   1024
#define TEMB  256
#define NL    4
#define D2    ((size_t)DIM * DIM)

#define EP_BIAS  0
#define EP_ADD   1
#define EP_GELUH 3
#define EP_HALF  4

__device__ float g_h  [BATCH * DIM];
__device__ float g_bp [NL * DIM];
__device__ float g_zero[16 * DIM];
__device__ __half g_adah[(size_t)BATCH * 16 * DIM];
__device__ __half g_xh [BATCH * DIM];
__device__ __half g_y  [BATCH * DIM];
__device__ __half g_st [BATCH * TEMB];
__device__ __half g_big[BATCH * 4 * DIM];
__device__ __half g_woh[NL * D2];
__device__ __half g_wvt[NL * D2];
__device__ __half g_wp [NL * D2];
#define WTOT (38 * D2)
__device__ __half g_w[WTOT];

__device__ __forceinline__ uint32_t smem_u32(const void* p) {
    uint32_t a;
    asm("{ .reg .u64 t; cvta.to.shared.u64 t, %1; cvt.u32.u64 %0, t; }" : "=r"(a) : "l"(p));
    return a;
}
__device__ __forceinline__ void ldsm4(uint32_t* r, uint32_t a) {
    asm volatile("ldmatrix.sync.aligned.m8n8.x4.shared.b16 {%0,%1,%2,%3}, [%4];"
                 : "=r"(r[0]), "=r"(r[1]), "=r"(r[2]), "=r"(r[3]) : "r"(a));
}
__device__ __forceinline__ void mma16816(float* c, const uint32_t* a, const uint32_t* b) {
    asm volatile("mma.sync.aligned.m16n8k16.row.col.f32.f16.f16.f32 "
                 "{%0,%1,%2,%3}, {%4,%5,%6,%7}, {%8,%9}, {%0,%1,%2,%3};"
                 : "+f"(c[0]), "+f"(c[1]), "+f"(c[2]), "+f"(c[3])
                 : "r"(a[0]), "r"(a[1]), "r"(a[2]), "r"(a[3]), "r"(b[0]), "r"(b[1]));
}
__device__ __forceinline__ uint32_t pack2(__half a, __half b) {
    return (uint32_t)__half_as_ushort(a) | ((uint32_t)__half_as_ushort(b) << 16);
}
__device__ __forceinline__ float gelu1(float v) {
    return 0.5f * v * (1.f + erff(v * 0.70710678118654752f));
}

// ---- GEMM: C[M,N] = A[M,K] @ W[N,K]^T, fp16 in, fp32 accum ----
#define BM 128
#define BN 256
#define OW  16384
#define STG 49152
#define NSTAGE 4
#define SMEMSZ (NSTAGE * STG)
#define NTHR 512

__device__ __forceinline__ void ld_tile(uint32_t tb, const __half* __restrict__ g,
                                        int row0, int K, int k0, int nrows, int tid) {
    const char* base = (const char*)(g + (size_t)row0 * K + k0);
    const size_t rs = (size_t)K * 2;
    #pragma unroll
    for (int i = tid; i < nrows * 8; i += NTHR) {
        int r = i >> 3, c2 = i & 7;
        uint32_t off = (uint32_t)(r * 128 + c2 * 16);
        uint32_t dst = tb + (off ^ ((off >> 3) & 0x70));
        asm volatile("cp.async.cg.shared.global [%0], [%1], 16;"
                     :: "r"(dst), "l"(base + (size_t)r * rs + c2 * 16));
    }
}
__device__ __forceinline__ void load_stage(uint32_t sb, int s,
    const __half* A, const __half* W, int bm, int bn, int K, int c, int tid) {
    uint32_t st = sb + (uint32_t)s * STG;
    ld_tile(st,      A, bm, K, c * 64, 128, tid);
    ld_tile(st + OW, W, bn, K, c * 64, 256, tid);
    asm volatile("cp.async.commit_group;" ::: "memory");
}

template<int EP>
__global__ void __launch_bounds__(NTHR, 1)
gemm_tc(const __half* __restrict__ A, const __half* __restrict__ W,
        const float* __restrict__ bias, const float* __restrict__ extra,
        float* __restrict__ Cf, __half* __restrict__ Oh,
        int N, int K, size_t zA, size_t zW, size_t zC)
{
    extern __shared__ __align__(1024) char smem[];
    uint32_t sb = smem_u32(smem);
    const int tid = threadIdx.x, lane = tid & 31, wid = tid >> 5;
    const int bm = blockIdx.y * BM, bn = blockIdx.x * BN;
    const size_t z = blockIdx.z;
    A += z * zA; W += z * zW;

    float acc[2][8][4] = {};

    const int wm = (wid & 3) * 32, wn = (wid >> 2) * 64;
    const int arow = (lane & 7) + ((lane >> 3) & 1) * 8;
    const int ac   = (lane >> 4) & 1;
    const uint32_t axor = (uint32_t)((arow & 7) << 4);
    uint32_t aterm[2];
    #pragma unroll
    for (int mt = 0; mt < 2; mt++) aterm[mt] = (uint32_t)((wm + mt * 16 + arow) * 128);

    const int brow = lane & 7;
    const int bk   = (lane >> 3) & 1;
    const int bn8  = (lane >> 4) & 1;
    const uint32_t bxor = (uint32_t)(brow << 4);
    uint32_t bterm[4];
    #pragma unroll
    for (int ntp = 0; ntp < 4; ntp++)
        bterm[ntp] = (uint32_t)((wn + ntp * 16 + bn8 * 8 + brow) * 128);

    const int nch = K >> 6;
    load_stage(sb, 0, A, W, bm, bn, K, 0, tid);
    load_stage(sb, 1, A, W, bm, bn, K, 1, tid);
    load_stage(sb, 2, A, W, bm, bn, K, 2, tid);

    for (int c = 0; c < nch; c++) {
        asm volatile("cp.async.wait_group 2;" ::: "memory");
        __syncthreads();
        if (c + 3 < nch) load_stage(sb, (c + 3) % NSTAGE, A, W, bm, bn, K, c + 3, tid);
        else             asm volatile("cp.async.commit_group;" ::: "memory");

        uint32_t st = sb + (uint32_t)(c % NSTAGE) * STG;
        #pragma unroll
        for (int ks = 0; ks < 4; ks++) {
            const uint32_t ka = (uint32_t)(ks * 32 + ac * 16);
            const uint32_t kb = (uint32_t)(ks * 32 + bk * 16);
            uint32_t fb[8][2];
            #pragma unroll
            for (int ntp = 0; ntp < 4; ntp++)
                ldsm4(&fb[2 * ntp][0], st + OW + bterm[ntp] + (kb ^ bxor));
            #pragma unroll
            for (int mt = 0; mt < 2; mt++) {
                uint32_t fa[4];
                ldsm4(fa, st + aterm[mt] + (ka ^ axor));
                #pragma unroll
                for (int nt = 0; nt < 8; nt++)
                    mma16816(acc[mt][nt], fa, fb[nt]);
            }
        }
    }

    const int r0b = bm + wm + (lane >> 2);
    const int c0b = bn + wn + 2 * (lane & 3);
    #pragma unroll
    for (int mt = 0; mt < 2; mt++) {
        const int row0 = r0b + mt * 16, row1 = row0 + 8;
        #pragma unroll
        for (int nt = 0; nt < 8; nt++) {
            const int col = c0b + nt * 8;
            const float b0 = bias[col], b1 = bias[col + 1];
            float v00 = acc[mt][nt][0] + b0, v01 = acc[mt][nt][1] + b1;
            float v10 = acc[mt][nt][2] + b0, v11 = acc[mt][nt][3] + b1;
            const size_t g0 = z * zC + (size_t)row0 * N + col;
            const size_t g1 = z * zC + (size_t)row1 * N + col;

            if (EP == EP_GELUH) {
                v00 = gelu1(v00); v01 = gelu1(v01); v10 = gelu1(v10); v11 = gelu1(v11);
            }
            if (EP == EP_GELUH || EP == EP_HALF) {
                *(uint32_t*)(Oh + g0) = pack2(__float2half_rn(v00), __float2half_rn(v01));
                *(uint32_t*)(Oh + g1) = pack2(__float2half_rn(v10), __float2half_rn(v11));
            } else if (EP == EP_ADD) {
                float2 e0 = *(const float2*)(extra + g0);
                float2 e1 = *(const float2*)(extra + g1);
                *(float2*)(Cf + g0) = make_float2(v00 + e0.x, v01 + e0.y);
                *(float2*)(Cf + g1) = make_float2(v10 + e1.x, v11 + e1.y);
            } else {
                *(float2*)(Cf + g0) = make_float2(v00, v01);
                *(float2*)(Cf + g1) = make_float2(v10, v11);
            }
        }
    }
}

// ---- elementwise / small kernels ----
template<int SILU>
__global__ void cvt_k(const float* __restrict__ s, __half* __restrict__ o, int n) {
    int i = (blockIdx.x * blockDim.x + threadIdx.x) * 8;
    if (i >= n) return;
    float4 a = *(const float4*)(s + i);
    float4 b = *(const float4*)(s + i + 4);
    if (SILU) {
        a.x /= (1.f + expf(-a.x)); a.y /= (1.f + expf(-a.y));
        a.z /= (1.f + expf(-a.z)); a.w /= (1.f + expf(-a.w));
        b.x /= (1.f + expf(-b.x)); b.y /= (1.f + expf(-b.y));
        b.z /= (1.f + expf(-b.z)); b.w /= (1.f + expf(-b.w));
    }
    uint4 r;
    r.x = pack2(__float2half_rn(a.x), __float2half_rn(a.y));
    r.y = pack2(__float2half_rn(a.z), __float2half_rn(a.w));
    r.z = pack2(__float2half_rn(b.x), __float2half_rn(b.y));
    r.w = pack2(__float2half_rn(b.z), __float2half_rn(b.w));
    *(uint4*)(o + i) = r;
}

__global__ void transpose_wv(const float* __restrict__ wqkv, __half* __restrict__ wvt) {
    __shared__ float tile[32][33];
    const int l = blockIdx.z;
    const float* src = wqkv + (size_t)l * 3 * D2 + 2 * D2;
    __half* dst = wvt + (size_t)l * D2;
    const int k0 = blockIdx.x * 32, m0 = blockIdx.y * 32;
    const int tx = threadIdx.x, ty = threadIdx.y;
    #pragma unroll
    for (int i = 0; i < 4; i++) {
        int r = ty + i * 8;
        tile[r][tx] = src[(size_t)(m0 + r) * DIM + k0 + tx];
    }
    __syncthreads();
    #pragma unroll
    for (int i = 0; i < 4; i++) {
        int r = ty + i * 8;
        dst[(size_t)(k0 + r) * DIM + m0 + tx] = __float2half_rn(tile[tx][r]);
    }
}

__global__ __launch_bounds__(256) void bprime_k(
    const float* __restrict__ wo, const float* __restrict__ bqkv,
    const float* __restrict__ bo, float* __restrict__ bp)
{
    const int n = blockIdx.x, l = blockIdx.y, t = threadIdx.x;
    const float* wr = wo + (size_t)l * D2 + (size_t)n * DIM;
    const float* bv = bqkv + (size_t)l * 3 * DIM + 2 * DIM;
    float s = 0.f;
    for (int k = t; k < DIM; k += 256) s += wr[k] * bv[k];
    #pragma unroll
    for (int o = 16; o; o >>= 1) s += __shfl_xor_sync(0xffffffffu, s, o);
    __shared__ float ss[8];
    if ((t & 31) == 0) ss[t >> 5] = s;
    __syncthreads();
    if (t == 0) {
        float r = 0.f;
        #pragma unroll
        for (int i = 0; i < 8; i++) r += ss[i];
        bp[l * DIM + n] = r + bo[l * DIM + n];
    }
}

__device__ __forceinline__ void ln_apply(
    float4* v, int row, int lane,
    const float* __restrict__ g, const float* __restrict__ b,
    const __half* __restrict__ ada, int so, int sho, __half* __restrict__ oh)
{
    float s = 0.f, q = 0.f;
    #pragma unroll
    for (int i = 0; i < 8; i++) {
        s += v[i].x + v[i].y + v[i].z + v[i].w;
        q += v[i].x*v[i].x + v[i].y*v[i].y + v[i].z*v[i].z + v[i].w*v[i].w;
    }
    #pragma unroll
    for (int o = 16; o; o >>= 1) {
        s += __shfl_xor_sync(0xffffffffu, s, o);
        q += __shfl_xor_sync(0xffffffffu, q, o);
    }
    const float m   = s * (1.f / DIM);
    const float inv = rsqrtf(q * (1.f / DIM) - m * m + 1e-5f);
    const __half* ar = ada ? ada + (size_t)row * (16 * DIM) : nullptr;
    #pragma unroll
    for (int i = 0; i < 8; i++) {
        const int e = (i * 32 + lane) * 4;
        float4 g4 = ((const float4*)g)[i * 32 + lane];
        float4 b4 = ((const float4*)b)[i * 32 + lane];
        float o0 = (v[i].x - m) * inv * g4.x + b4.x;
        float o1 = (v[i].y - m) * inv * g4.y + b4.y;
        float o2 = (v[i].z - m) * inv * g4.z + b4.z;
        float o3 = (v[i].w - m) * inv * g4.w + b4.w;
        if (ar) {
            __half2 sa = ((const __half2*)(ar + so + e))[0];
            __half2 sb2 = ((const __half2*)(ar + so + e))[1];
            __half2 ha = ((const __half2*)(ar + sho + e))[0];
            __half2 hb = ((const __half2*)(ar + sho + e))[1];
            o0 = o0 * (1.f + __low2float(sa))  + __low2float(ha);
            o1 = o1 * (1.f + __high2float(sa)) + __high2float(ha);
            o2 = o2 * (1.f + __low2float(sb2)) + __low2float(hb);
            o3 = o3 * (1.f + __high2float(sb2))+ __high2float(hb);
        }
        ((uint2*)(oh + (size_t)row * DIM))[i * 32 + lane] =
            make_uint2(pack2(__float2half_rn(o0), __float2half_rn(o1)),
                       pack2(__float2half_rn(o2), __float2half_rn(o3)));
    }
}

__global__ __launch_bounds__(256) void ln_half_k(
    const float* __restrict__ h, const float* __restrict__ g,
    const float* __restrict__ b, const __half* __restrict__ ada,
    int so, int sho, __half* __restrict__ oh)
{
    const int lane = threadIdx.x & 31;
    const int row  = blockIdx.x * 8 + (threadIdx.x >> 5);
    const float4* hr = (const float4*)(h + (size_t)row * DIM);
    float4 v[8];
    #pragma unroll
    for (int i = 0; i < 8; i++) v[i] = hr[i * 32 + lane];
    ln_apply(v, row, lane, g, b, ada, so, sho, oh);
}

__global__ __launch_bounds__(256) void ln_res_k(
    float* __restrict__ h, const __half* __restrict__ y,
    const float* __restrict__ g, const float* __restrict__ b,
    const __half* __restrict__ ada, int so, int sho, __half* __restrict__ oh)
{
    const int lane = threadIdx.x & 31;
    const int row  = blockIdx.x * 8 + (threadIdx.x >> 5);
    float4* hr = (float4*)(h + (size_t)row * DIM);
    const uint2* yr = (const uint2*)(y + (size_t)row * DIM);
    float4 v[8];
    #pragma unroll
    for (int i = 0; i < 8; i++) {
        float4 t = hr[i * 32 + lane];
        uint2 yv = yr[i * 32 + lane];
        __half2 y0 = *(__half2*)&yv.x, y1 = *(__half2*)&yv.y;
        t.x += __low2float(y0); t.y += __high2float(y0);
        t.z += __low2float(y1); t.w += __high2float(y1);
        hr[i * 32 + lane] = t;
        v[i] = t;
    }
    ln_apply(v, row, lane, g, b, ada, so, sho, oh);
}

// ---- launch ----
extern "C" void kernel_launch(void* const* d_in, const int* in_sizes, int n_in,
                              void* d_out, int out_size)
{
    const float* x        = (const float*)d_in[0];
    const float* t_emb    = (const float*)d_in[1];
    const float* condition= (const float*)d_in[2];
    const float* in_w     = (const float*)d_in[3];
    const float* in_b     = (const float*)d_in[4];
    const float* ln1_g    = (const float*)d_in[5];
    const float* ln1_b    = (const float*)d_in[6];
    const float* wqkv     = (const float*)d_in[7];
    const float* bqkv     = (const float*)d_in[8];
    const float* wo       = (const float*)d_in[9];
    const float* bo       = (const float*)d_in[10];
    const float* ln2_g    = (const float*)d_in[11];
    const float* ln2_b    = (const float*)d_in[12];
    const float* w1       = (const float*)d_in[13];
    const float* b1       = (const float*)d_in[14];
    const float* w2       = (const float*)d_in[15];
    const float* b2       = (const float*)d_in[16];
    const float* ada_w    = (const float*)d_in[17];
    const float* ada_b    = (const float*)d_in[18];
    const float* out_ln_g = (const float*)d_in[19];
    const float* out_ln_b = (const float*)d_in[20];
    const float* out_w    = (const float*)d_in[21];
    const float* out_b    = (const float*)d_in[22];

    float *h, *bp, *zero;
    __half *adah,*xh,*y,*st,*big,*w,*woh,*wvt,*wp;
    cudaGetSymbolAddress((void**)&h,    g_h);
    cudaGetSymbolAddress((void**)&bp,   g_bp);
    cudaGetSymbolAddress((void**)&zero, g_zero);
    cudaGetSymbolAddress((void**)&adah, g_adah);
    cudaGetSymbolAddress((void**)&xh,   g_xh);
    cudaGetSymbolAddress((void**)&y,    g_y);
    cudaGetSymbolAddress((void**)&st,   g_st);
    cudaGetSymbolAddress((void**)&big,  g_big);
    cudaGetSymbolAddress((void**)&w,    g_w);
    cudaGetSymbolAddress((void**)&woh,  g_woh);
    cudaGetSymbolAddress((void**)&wvt,  g_wvt);
    cudaGetSymbolAddress((void**)&wp,   g_wp);

    cudaFuncSetAttribute(gemm_tc<EP_BIAS>,  cudaFuncAttributeMaxDynamicSharedMemorySize, SMEMSZ);
    cudaFuncSetAttribute(gemm_tc<EP_ADD>,   cudaFuncAttributeMaxDynamicSharedMemorySize, SMEMSZ);
    cudaFuncSetAttribute(gemm_tc<EP_GELUH>, cudaFuncAttributeMaxDynamicSharedMemorySize, SMEMSZ);
    cudaFuncSetAttribute(gemm_tc<EP_HALF>,  cudaFuncAttributeMaxDynamicSharedMemorySize, SMEMSZ);

    const size_t OFF_ADA = D2, OFF_W1 = 5 * D2, OFF_W2 = 21 * D2, OFF_OUT = 37 * D2;

    const int sb = 256;
    auto cvtS = [&](cudaStream_t sN, const float* src, __half* o, size_t n) {
        cvt_k<0><<<(int)((n / 8 + sb - 1) / sb), sb, 0, sN>>>(src, o, (int)n);
    };

    const dim3 blk(NTHR);
    const dim3 gD  (DIM / BN, BATCH / BM);
    const dim3 g4D (4 * DIM / BN, BATCH / BM);
    const dim3 gAda(16 * DIM / BN, BATCH / BM);
    const dim3 gWp (DIM / BN, DIM / BM, NL);

    // ---- fork: side stream runs the wp/in-proj chain + big weight cvts,
    // overlapping the ada GEMM on the main stream.
    cudaStream_t s2;
    cudaStreamCreateWithFlags(&s2, cudaStreamNonBlocking);
    cudaEvent_t eF, eJ;
    cudaEventCreateWithFlags(&eF, cudaEventDisableTiming);
    cudaEventCreateWithFlags(&eJ, cudaEventDisableTiming);
    cudaEventRecord(eF, 0);
    cudaStreamWaitEvent(s2, eF, 0);

    // side stream: chain 2 (independent of ada)
    cvtS(s2, x,    xh,  (size_t)BATCH * DIM);
    cvtS(s2, in_w, w,   D2);
    cvtS(s2, wo,   woh, 4 * D2);
    transpose_wv<<<dim3(32, 32, NL), dim3(32, 8), 0, s2>>>(wqkv, wvt);
    bprime_k<<<dim3(DIM, NL), 256, 0, s2>>>(wo, bqkv, bo, bp);
    gemm_tc<EP_HALF><<<gWp, blk, SMEMSZ, s2>>>(woh, wvt, zero, nullptr, nullptr, wp,
                                               DIM, DIM, D2, D2, D2);
    gemm_tc<EP_ADD><<<gD, blk, SMEMSZ, s2>>>(xh, w, in_b, condition, h, nullptr,
                                             DIM, DIM, 0, 0, 0);
    cvtS(s2, w1,    w + OFF_W1,  16 * D2);
    cvtS(s2, w2,    w + OFF_W2,  16 * D2);
    cvtS(s2, out_w, w + OFF_OUT, D2);
    cudaEventRecord(eJ, s2);

    // main stream: chain 1 (ada)
    cvt_k<1><<<(BATCH * TEMB / 8 + sb - 1) / sb, sb>>>(t_emb, st, BATCH * TEMB);
    cvtS(0, ada_w, w + OFF_ADA, 4 * D2);
    gemm_tc<EP_HALF><<<gAda, blk, SMEMSZ>>>(st, w + OFF_ADA, ada_b, nullptr, nullptr, adah,
                                            16 * DIM, TEMB, 0, 0, 0);

    // join: first LN needs h (side) and adah (main)
    cudaStreamWaitEvent(0, eJ, 0);
    ln_half_k<<<BATCH / 8, 256>>>(h, ln1_g, ln1_b, adah, 0, DIM, xh);

    for (int l = 0; l < NL; l++) {
        const int ao = l * 4 * DIM;
        gemm_tc<EP_HALF><<<gD, blk, SMEMSZ>>>(xh, wp + (size_t)l * D2,
                                              bp + (size_t)l * DIM, nullptr, nullptr, y,
                                              DIM, DIM, 0, 0, 0);
        ln_res_k<<<BATCH / 8, 256>>>(h, y, ln2_g + (size_t)l * DIM, ln2_b + (size_t)l * DIM,
                                     adah, ao + 2 * DIM, ao + 3 * DIM, xh);
        gemm_tc<EP_GELUH><<<g4D, blk, SMEMSZ>>>(xh, w + OFF_W1 + (size_t)l * 4 * D2,
                                                b1 + (size_t)l * 4 * DIM, nullptr, nullptr, big,
                                                4 * DIM, DIM, 0, 0, 0);
        gemm_tc<EP_HALF><<<gD, blk, SMEMSZ>>>(big, w + OFF_W2 + (size_t)l * 4 * D2,
                                              b2 + (size_t)l * DIM, nullptr, nullptr, y,
                                              DIM, 4 * DIM, 0, 0, 0);
        if (l < NL - 1) {
            const int ao2 = (l + 1) * 4 * DIM;
            ln_res_k<<<BATCH / 8, 256>>>(h, y, ln1_g + (size_t)(l + 1) * DIM,
                                         ln1_b + (size_t)(l + 1) * DIM,
                                         adah, ao2, ao2 + DIM, xh);
        } else {
            ln_res_k<<<BATCH / 8, 256>>>(h, y, out_ln_g, out_ln_b, nullptr, 0, 0, xh);
        }
    }

    gemm_tc<EP_BIAS><<<gD, blk, SMEMSZ>>>(xh, w + OFF_OUT, out_b, nullptr,
                                          (float*)d_out, nullptr, DIM, DIM, 0, 0, 0);
}

// round 16
// speedup vs baseline: 1.0034x; 1.0004x over previous
#include <cuda_runtime.h>
#include <cuda_fp16.h>
#include <math.h>
#include <stdint.h>

#define BATCH 4096
#define DIM   1024
#define TEMB  256
#define NL    4
#define D2    ((size_t)DIM * DIM)

#define EP_BIAS  0
#define EP_ADD   1
#define EP_GELUH 3
#define EP_HALF  4

__device__ float g_h  [BATCH * DIM];
__device__ float g_bp [NL * DIM];
__device__ float g_zero[16 * DIM];
__device__ __half g_adah[(size_t)BATCH * 16 * DIM];
__device__ __half g_xh [BATCH * DIM];
__device__ __half g_y  [BATCH * DIM];
__device__ __half g_st [BATCH * TEMB];
__device__ __half g_big[BATCH * 4 * DIM];
__device__ __half g_woh[NL * D2];
__device__ __half g_wvt[NL * D2];
__device__ __half g_wp [NL * D2];
#define WTOT (38 * D2)
__device__ __half g_w[WTOT];

__device__ __forceinline__ uint32_t smem_u32(const void* p) {
    uint32_t a;
    asm("{ .reg .u64 t; cvta.to.shared.u64 t, %1; cvt.u32.u64 %0, t; }" : "=r"(a) : "l"(p));
    return a;
}
__device__ __forceinline__ void ldsm4(uint32_t* r, uint32_t a) {
    asm volatile("ldmatrix.sync.aligned.m8n8.x4.shared.b16 {%0,%1,%2,%3}, [%4];"
                 : "=r"(r[0]), "=r"(r[1]), "=r"(r[2]), "=r"(r[3]) : "r"(a));
}
__device__ __forceinline__ void mma16816(float* c, const uint32_t* a, const uint32_t* b) {
    asm volatile("mma.sync.aligned.m16n8k16.row.col.f32.f16.f16.f32 "
                 "{%0,%1,%2,%3}, {%4,%5,%6,%7}, {%8,%9}, {%0,%1,%2,%3};"
                 : "+f"(c[0]), "+f"(c[1]), "+f"(c[2]), "+f"(c[3])
                 : "r"(a[0]), "r"(a[1]), "r"(a[2]), "r"(a[3]), "r"(b[0]), "r"(b[1]));
}
__device__ __forceinline__ uint32_t pack2(__half a, __half b) {
    return (uint32_t)__half_as_ushort(a) | ((uint32_t)__half_as_ushort(b) << 16);
}
__device__ __forceinline__ float gelu1(float v) {
    return 0.5f * v * (1.f + erff(v * 0.70710678118654752f));
}

// ---- GEMM: C[M,N] = A[M,K] @ W[N,K]^T, fp16 in, fp32 accum ----
#define BM 128
#define BN 256
#define OW  16384
#define STG 49152
#define NSTAGE 4
#define SMEMSZ (NSTAGE * STG)
#define NTHR 512

__device__ __forceinline__ void ld_tile(uint32_t tb, const __half* __restrict__ g,
                                        int row0, int K, int k0, int nrows, int tid) {
    const char* base = (const char*)(g + (size_t)row0 * K + k0);
    const size_t rs = (size_t)K * 2;
    #pragma unroll
    for (int i = tid; i < nrows * 8; i += NTHR) {
        int r = i >> 3, c2 = i & 7;
        uint32_t off = (uint32_t)(r * 128 + c2 * 16);
        uint32_t dst = tb + (off ^ ((off >> 3) & 0x70));
        asm volatile("cp.async.cg.shared.global [%0], [%1], 16;"
                     :: "r"(dst), "l"(base + (size_t)r * rs + c2 * 16));
    }
}
__device__ __forceinline__ void load_stage(uint32_t sb, int s,
    const __half* A, const __half* W, int bm, int bn, int K, int c, int tid) {
    uint32_t st = sb + (uint32_t)s * STG;
    ld_tile(st,      A, bm, K, c * 64, 128, tid);
    ld_tile(st + OW, W, bn, K, c * 64, 256, tid);
    asm volatile("cp.async.commit_group;" ::: "memory");
}

template<int EP>
__global__ void __launch_bounds__(NTHR, 1)
gemm_tc(const __half* __restrict__ A, const __half* __restrict__ W,
        const float* __restrict__ bias, const float* __restrict__ extra,
        float* __restrict__ Cf, __half* __restrict__ Oh,
        int N, int K, size_t zA, size_t zW, size_t zC)
{
    extern __shared__ __align__(1024) char smem[];
    uint32_t sb = smem_u32(smem);
    const int tid = threadIdx.x, lane = tid & 31, wid = tid >> 5;
    const int bm = blockIdx.y * BM, bn = blockIdx.x * BN;
    const size_t z = blockIdx.z;
    A += z * zA; W += z * zW;

    float acc[2][8][4] = {};

    const int wm = (wid & 3) * 32, wn = (wid >> 2) * 64;
    const int arow = (lane & 7) + ((lane >> 3) & 1) * 8;
    const int ac   = (lane >> 4) & 1;
    const uint32_t axor = (uint32_t)((arow & 7) << 4);
    uint32_t aterm[2];
    #pragma unroll
    for (int mt = 0; mt < 2; mt++) aterm[mt] = (uint32_t)((wm + mt * 16 + arow) * 128);

    const int brow = lane & 7;
    const int bk   = (lane >> 3) & 1;
    const int bn8  = (lane >> 4) & 1;
    const uint32_t bxor = (uint32_t)(brow << 4);
    uint32_t bterm[4];
    #pragma unroll
    for (int ntp = 0; ntp < 4; ntp++)
        bterm[ntp] = (uint32_t)((wn + ntp * 16 + bn8 * 8 + brow) * 128);

    const int nch = K >> 6;
    load_stage(sb, 0, A, W, bm, bn, K, 0, tid);
    load_stage(sb, 1, A, W, bm, bn, K, 1, tid);
    load_stage(sb, 2, A, W, bm, bn, K, 2, tid);

    for (int c = 0; c < nch; c++) {
        asm volatile("cp.async.wait_group 2;" ::: "memory");
        __syncthreads();
        if (c + 3 < nch) load_stage(sb, (c + 3) % NSTAGE, A, W, bm, bn, K, c + 3, tid);
        else             asm volatile("cp.async.commit_group;" ::: "memory");

        uint32_t st = sb + (uint32_t)(c % NSTAGE) * STG;
        #pragma unroll
        for (int ks = 0; ks < 4; ks++) {
            const uint32_t ka = (uint32_t)(ks * 32 + ac * 16);
            const uint32_t kb = (uint32_t)(ks * 32 + bk * 16);
            uint32_t fb[8][2];
            #pragma unroll
            for (int ntp = 0; ntp < 4; ntp++)
                ldsm4(&fb[2 * ntp][0], st + OW + bterm[ntp] + (kb ^ bxor));
            #pragma unroll
            for (int mt = 0; mt < 2; mt++) {
                uint32_t fa[4];
                ldsm4(fa, st + aterm[mt] + (ka ^ axor));
                #pragma unroll
                for (int nt = 0; nt < 8; nt++)
                    mma16816(acc[mt][nt], fa, fb[nt]);
            }
        }
    }

    const int r0b = bm + wm + (lane >> 2);
    const int c0b = bn + wn + 2 * (lane & 3);
    #pragma unroll
    for (int mt = 0; mt < 2; mt++) {
        const int row0 = r0b + mt * 16, row1 = row0 + 8;
        #pragma unroll
        for (int nt = 0; nt < 8; nt++) {
            const int col = c0b + nt * 8;
            const float b0 = bias[col], b1 = bias[col + 1];
            float v00 = acc[mt][nt][0] + b0, v01 = acc[mt][nt][1] + b1;
            float v10 = acc[mt][nt][2] + b0, v11 = acc[mt][nt][3] + b1;
            const size_t g0 = z * zC + (size_t)row0 * N + col;
            const size_t g1 = z * zC + (size_t)row1 * N + col;

            if (EP == EP_GELUH) {
                v00 = gelu1(v00); v01 = gelu1(v01); v10 = gelu1(v10); v11 = gelu1(v11);
            }
            if (EP == EP_GELUH || EP == EP_HALF) {
                *(uint32_t*)(Oh + g0) = pack2(__float2half_rn(v00), __float2half_rn(v01));
                *(uint32_t*)(Oh + g1) = pack2(__float2half_rn(v10), __float2half_rn(v11));
            } else if (EP == EP_ADD) {
                float2 e0 = *(const float2*)(extra + g0);
                float2 e1 = *(const float2*)(extra + g1);
                *(float2*)(Cf + g0) = make_float2(v00 + e0.x, v01 + e0.y);
                *(float2*)(Cf + g1) = make_float2(v10 + e1.x, v11 + e1.y);
            } else {
                *(float2*)(Cf + g0) = make_float2(v00, v01);
                *(float2*)(Cf + g1) = make_float2(v10, v11);
            }
        }
    }
}

// ---- elementwise / small kernels ----
template<int SILU>
__global__ void cvt_k(const float* __restrict__ s, __half* __restrict__ o, int n) {
    int i = (blockIdx.x * blockDim.x + threadIdx.x) * 8;
    if (i >= n) return;
    float4 a = *(const float4*)(s + i);
    float4 b = *(const float4*)(s + i + 4);
    if (SILU) {
        a.x /= (1.f + expf(-a.x)); a.y /= (1.f + expf(-a.y));
        a.z /= (1.f + expf(-a.z)); a.w /= (1.f + expf(-a.w));
        b.x /= (1.f + expf(-b.x)); b.y /= (1.f + expf(-b.y));
        b.z /= (1.f + expf(-b.z)); b.w /= (1.f + expf(-b.w));
    }
    uint4 r;
    r.x = pack2(__float2half_rn(a.x), __float2half_rn(a.y));
    r.y = pack2(__float2half_rn(a.z), __float2half_rn(a.w));
    r.z = pack2(__float2half_rn(b.x), __float2half_rn(b.y));
    r.w = pack2(__float2half_rn(b.z), __float2half_rn(b.w));
    *(uint4*)(o + i) = r;
}

// wvt[l][k][m] = wqkv[l][2D+m][k], vectorized half2 stores.
// block (32,8), tile = 32 k x 64 m. grid (DIM/32, DIM/64, NL).
__global__ void transpose_wv(const float* __restrict__ wqkv, __half* __restrict__ wvt) {
    __shared__ float tile[32][65];      // [k][m], pad -> conflict-free loads
    const int l = blockIdx.z;
    const float* src = wqkv + (size_t)l * 3 * D2 + 2 * D2;
    __half* dst = wvt + (size_t)l * D2;
    const int k0 = blockIdx.x * 32, m0 = blockIdx.y * 64;
    const int tx = threadIdx.x, ty = threadIdx.y;
    #pragma unroll
    for (int i = 0; i < 8; i++) {
        int m = ty + i * 8;             // 0..63
        tile[tx][m] = src[(size_t)(m0 + m) * DIM + k0 + tx];
    }
    __syncthreads();
    #pragma unroll
    for (int i = 0; i < 4; i++) {
        int k = ty * 4 + i;             // 0..31
        __half2 v = __floats2half2_rn(tile[k][2 * tx], tile[k][2 * tx + 1]);
        *(__half2*)(dst + (size_t)(k0 + k) * DIM + m0 + 2 * tx) = v;
    }
}

__global__ __launch_bounds__(256) void bprime_k(
    const float* __restrict__ wo, const float* __restrict__ bqkv,
    const float* __restrict__ bo, float* __restrict__ bp)
{
    const int n = blockIdx.x, l = blockIdx.y, t = threadIdx.x;
    const float* wr = wo + (size_t)l * D2 + (size_t)n * DIM;
    const float* bv = bqkv + (size_t)l * 3 * DIM + 2 * DIM;
    float s = 0.f;
    for (int k = t; k < DIM; k += 256) s += wr[k] * bv[k];
    #pragma unroll
    for (int o = 16; o; o >>= 1) s += __shfl_xor_sync(0xffffffffu, s, o);
    __shared__ float ss[8];
    if ((t & 31) == 0) ss[t >> 5] = s;
    __syncthreads();
    if (t == 0) {
        float r = 0.f;
        #pragma unroll
        for (int i = 0; i < 8; i++) r += ss[i];
        bp[l * DIM + n] = r + bo[l * DIM + n];
    }
}

__device__ __forceinline__ void ln_apply(
    float4* v, int row, int lane,
    const float* __restrict__ g, const float* __restrict__ b,
    const __half* __restrict__ ada, int so, int sho, __half* __restrict__ oh)
{
    float s = 0.f, q = 0.f;
    #pragma unroll
    for (int i = 0; i < 8; i++) {
        s += v[i].x + v[i].y + v[i].z + v[i].w;
        q += v[i].x*v[i].x + v[i].y*v[i].y + v[i].z*v[i].z + v[i].w*v[i].w;
    }
    #pragma unroll
    for (int o = 16; o; o >>= 1) {
        s += __shfl_xor_sync(0xffffffffu, s, o);
        q += __shfl_xor_sync(0xffffffffu, q, o);
    }
    const float m   = s * (1.f / DIM);
    const float inv = rsqrtf(q * (1.f / DIM) - m * m + 1e-5f);
    const __half* ar = ada ? ada + (size_t)row * (16 * DIM) : nullptr;
    #pragma unroll
    for (int i = 0; i < 8; i++) {
        const int e = (i * 32 + lane) * 4;
        float4 g4 = ((const float4*)g)[i * 32 + lane];
        float4 b4 = ((const float4*)b)[i * 32 + lane];
        float o0 = (v[i].x - m) * inv * g4.x + b4.x;
        float o1 = (v[i].y - m) * inv * g4.y + b4.y;
        float o2 = (v[i].z - m) * inv * g4.z + b4.z;
        float o3 = (v[i].w - m) * inv * g4.w + b4.w;
        if (ar) {
            __half2 sa = ((const __half2*)(ar + so + e))[0];
            __half2 sb2 = ((const __half2*)(ar + so + e))[1];
            __half2 ha = ((const __half2*)(ar + sho + e))[0];
            __half2 hb = ((const __half2*)(ar + sho + e))[1];
            o0 = o0 * (1.f + __low2float(sa))  + __low2float(ha);
            o1 = o1 * (1.f + __high2float(sa)) + __high2float(ha);
            o2 = o2 * (1.f + __low2float(sb2)) + __low2float(hb);
            o3 = o3 * (1.f + __high2float(sb2))+ __high2float(hb);
        }
        ((uint2*)(oh + (size_t)row * DIM))[i * 32 + lane] =
            make_uint2(pack2(__float2half_rn(o0), __float2half_rn(o1)),
                       pack2(__float2half_rn(o2), __float2half_rn(o3)));
    }
}

__global__ __launch_bounds__(256) void ln_half_k(
    const float* __restrict__ h, const float* __restrict__ g,
    const float* __restrict__ b, const __half* __restrict__ ada,
    int so, int sho, __half* __restrict__ oh)
{
    const int lane = threadIdx.x & 31;
    const int row  = blockIdx.x * 8 + (threadIdx.x >> 5);
    const float4* hr = (const float4*)(h + (size_t)row * DIM);
    float4 v[8];
    #pragma unroll
    for (int i = 0; i < 8; i++) v[i] = hr[i * 32 + lane];
    ln_apply(v, row, lane, g, b, ada, so, sho, oh);
}

// residual + LN; WH=0 skips the h write-back (used for the final out-LN)
template<int WH>
__global__ __launch_bounds__(256) void ln_res_k(
    float* __restrict__ h, const __half* __restrict__ y,
    const float* __restrict__ g, const float* __restrict__ b,
    const __half* __restrict__ ada, int so, int sho, __half* __restrict__ oh)
{
    const int lane = threadIdx.x & 31;
    const int row  = blockIdx.x * 8 + (threadIdx.x >> 5);
    float4* hr = (float4*)(h + (size_t)row * DIM);
    const uint2* yr = (const uint2*)(y + (size_t)row * DIM);
    float4 v[8];
    #pragma unroll
    for (int i = 0; i < 8; i++) {
        float4 t = hr[i * 32 + lane];
        uint2 yv = yr[i * 32 + lane];
        __half2 y0 = *(__half2*)&yv.x, y1 = *(__half2*)&yv.y;
        t.x += __low2float(y0); t.y += __high2float(y0);
        t.z += __low2float(y1); t.w += __high2float(y1);
        if (WH) hr[i * 32 + lane] = t;
        v[i] = t;
    }
    ln_apply(v, row, lane, g, b, ada, so, sho, oh);
}

// ---- launch ----
extern "C" void kernel_launch(void* const* d_in, const int* in_sizes, int n_in,
                              void* d_out, int out_size)
{
    const float* x        = (const float*)d_in[0];
    const float* t_emb    = (const float*)d_in[1];
    const float* condition= (const float*)d_in[2];
    const float* in_w     = (const float*)d_in[3];
    const float* in_b     = (const float*)d_in[4];
    const float* ln1_g    = (const float*)d_in[5];
    const float* ln1_b    = (const float*)d_in[6];
    const float* wqkv     = (const float*)d_in[7];
    const float* bqkv     = (const float*)d_in[8];
    const float* wo       = (const float*)d_in[9];
    const float* bo       = (const float*)d_in[10];
    const float* ln2_g    = (const float*)d_in[11];
    const float* ln2_b    = (const float*)d_in[12];
    const float* w1       = (const float*)d_in[13];
    const float* b1       = (const float*)d_in[14];
    const float* w2       = (const float*)d_in[15];
    const float* b2       = (const float*)d_in[16];
    const float* ada_w    = (const float*)d_in[17];
    const float* ada_b    = (const float*)d_in[18];
    const float* out_ln_g = (const float*)d_in[19];
    const float* out_ln_b = (const float*)d_in[20];
    const float* out_w    = (const float*)d_in[21];
    const float* out_b    = (const float*)d_in[22];

    float *h, *bp, *zero;
    __half *adah,*xh,*y,*st,*big,*w,*woh,*wvt,*wp;
    cudaGetSymbolAddress((void**)&h,    g_h);
    cudaGetSymbolAddress((void**)&bp,   g_bp);
    cudaGetSymbolAddress((void**)&zero, g_zero);
    cudaGetSymbolAddress((void**)&adah, g_adah);
    cudaGetSymbolAddress((void**)&xh,   g_xh);
    cudaGetSymbolAddress((void**)&y,    g_y);
    cudaGetSymbolAddress((void**)&st,   g_st);
    cudaGetSymbolAddress((void**)&big,  g_big);
    cudaGetSymbolAddress((void**)&w,    g_w);
    cudaGetSymbolAddress((void**)&woh,  g_woh);
    cudaGetSymbolAddress((void**)&wvt,  g_wvt);
    cudaGetSymbolAddress((void**)&wp,   g_wp);

    cudaFuncSetAttribute(gemm_tc<EP_BIAS>,  cudaFuncAttributeMaxDynamicSharedMemorySize, SMEMSZ);
    cudaFuncSetAttribute(gemm_tc<EP_ADD>,   cudaFuncAttributeMaxDynamicSharedMemorySize, SMEMSZ);
    cudaFuncSetAttribute(gemm_tc<EP_GELUH>, cudaFuncAttributeMaxDynamicSharedMemorySize, SMEMSZ);
    cudaFuncSetAttribute(gemm_tc<EP_HALF>,  cudaFuncAttributeMaxDynamicSharedMemorySize, SMEMSZ);

    const size_t OFF_ADA = D2, OFF_W1 = 5 * D2, OFF_W2 = 21 * D2, OFF_OUT = 37 * D2;

    const int sb = 256;
    auto cvtS = [&](cudaStream_t sN, const float* src, __half* o, size_t n) {
        cvt_k<0><<<(int)((n / 8 + sb - 1) / sb), sb, 0, sN>>>(src, o, (int)n);
    };

    const dim3 blk(NTHR);
    const dim3 gD  (DIM / BN, BATCH / BM);
    const dim3 g4D (4 * DIM / BN, BATCH / BM);
    const dim3 gAda(16 * DIM / BN, BATCH / BM);
    const dim3 gWp (DIM / BN, DIM / BM, NL);

    // fork (R13 layout, best measured): big weight cvts on side stream
    cudaStream_t s2;
    cudaStreamCreateWithFlags(&s2, cudaStreamNonBlocking);
    cudaEvent_t eF, eJ;
    cudaEventCreateWithFlags(&eF, cudaEventDisableTiming);
    cudaEventCreateWithFlags(&eJ, cudaEventDisableTiming);
    cudaEventRecord(eF, 0);
    cudaStreamWaitEvent(s2, eF, 0);
    cvtS(s2, w1,    w + OFF_W1,  16 * D2);
    cvtS(s2, w2,    w + OFF_W2,  16 * D2);
    cvtS(s2, out_w, w + OFF_OUT, D2);
    cudaEventRecord(eJ, s2);

    cvtS(0, x, xh, (size_t)BATCH * DIM);
    cvt_k<1><<<(BATCH * TEMB / 8 + sb - 1) / sb, sb>>>(t_emb, st, BATCH * TEMB);
    cvtS(0, in_w,  w,           D2);
    cvtS(0, ada_w, w + OFF_ADA, 4 * D2);
    cvtS(0, wo,    woh,         4 * D2);
    transpose_wv<<<dim3(DIM / 32, DIM / 64, NL), dim3(32, 8)>>>(wqkv, wvt);
    bprime_k<<<dim3(DIM, NL), 256>>>(wo, bqkv, bo, bp);

    gemm_tc<EP_HALF><<<gWp, blk, SMEMSZ>>>(woh, wvt, zero, nullptr, nullptr, wp,
                                           DIM, DIM, D2, D2, D2);
    gemm_tc<EP_HALF><<<gAda, blk, SMEMSZ>>>(st, w + OFF_ADA, ada_b, nullptr, nullptr, adah,
                                            16 * DIM, TEMB, 0, 0, 0);
    gemm_tc<EP_ADD><<<gD, blk, SMEMSZ>>>(xh, w, in_b, condition, h, nullptr,
                                         DIM, DIM, 0, 0, 0);
    ln_half_k<<<BATCH / 8, 256>>>(h, ln1_g, ln1_b, adah, 0, DIM, xh);

    cudaStreamWaitEvent(0, eJ, 0);

    for (int l = 0; l < NL; l++) {
        const int ao = l * 4 * DIM;
        gemm_tc<EP_HALF><<<gD, blk, SMEMSZ>>>(xh, wp + (size_t)l * D2,
                                              bp + (size_t)l * DIM, nullptr, nullptr, y,
                                              DIM, DIM, 0, 0, 0);
        ln_res_k<1><<<BATCH / 8, 256>>>(h, y, ln2_g + (size_t)l * DIM, ln2_b + (size_t)l * DIM,
                                        adah, ao + 2 * DIM, ao + 3 * DIM, xh);
        gemm_tc<EP_GELUH><<<g4D, blk, SMEMSZ>>>(xh, w + OFF_W1 + (size_t)l * 4 * D2,
                                                b1 + (size_t)l * 4 * DIM, nullptr, nullptr, big,
                                                4 * DIM, DIM, 0, 0, 0);
        gemm_tc<EP_HALF><<<gD, blk, SMEMSZ>>>(big, w + OFF_W2 + (size_t)l * 4 * D2,
                                              b2 + (size_t)l * DIM, nullptr, nullptr, y,
                                              DIM, 4 * DIM, 0, 0, 0);
        if (l < NL - 1) {
            const int ao2 = (l + 1) * 4 * DIM;
            ln_res_k<1><<<BATCH / 8, 256>>>(h, y, ln1_g + (size_t)(l + 1) * DIM,
                                            ln1_b + (size_t)(l + 1) * DIM,
                                            adah, ao2, ao2 + DIM, xh);
        } else {
            // final out-LN: h is dead afterwards -> skip write-back
            ln_res_k<0><<<BATCH / 8, 256>>>(h, y, out_ln_g, out_ln_b, nullptr, 0, 0, xh);
        }
    }

    gemm_tc<EP_BIAS><<<gD, blk, SMEMSZ>>>(xh, w + OFF_OUT, out_b, nullptr,
                                          (float*)d_out, nullptr, DIM, DIM, 0, 0, 0);
}

// round 17
// speedup vs baseline: 1.0160x; 1.0126x over previous
#include <cuda_runtime.h>
#include <cuda_fp16.h>
#include <math.h>
#include <stdint.h>

#define BATCH 4096
#define DIM   1024
#define TEMB  256
#define NL    4
#define D2    ((size_t)DIM * DIM)

#define EP_BIAS  0   // fp32 out + bias
#define EP_GELUH 3   // gelu -> fp16
#define EP_HALF  4   // fp16 out + bias
#define EP_ADDH  5   // fp16 out + bias + fp32 extra

__device__ float g_bp [NL * DIM];
__device__ float g_zero[16 * DIM];
__device__ __half g_h  [BATCH * DIM];           // residual stream, fp16
__device__ __half g_adah[(size_t)BATCH * 16 * DIM];
__device__ __half g_xh [BATCH * DIM];
__device__ __half g_y  [BATCH * DIM];
__device__ __half g_st [BATCH * TEMB];
__device__ __half g_big[BATCH * 4 * DIM];
__device__ __half g_woh[NL * D2];
__device__ __half g_wvt[NL * D2];
__device__ __half g_wp [NL * D2];
#define WTOT (38 * D2)
__device__ __half g_w[WTOT];

__device__ __forceinline__ uint32_t smem_u32(const void* p) {
    uint32_t a;
    asm("{ .reg .u64 t; cvta.to.shared.u64 t, %1; cvt.u32.u64 %0, t; }" : "=r"(a) : "l"(p));
    return a;
}
__device__ __forceinline__ void ldsm4(uint32_t* r, uint32_t a) {
    asm volatile("ldmatrix.sync.aligned.m8n8.x4.shared.b16 {%0,%1,%2,%3}, [%4];"
                 : "=r"(r[0]), "=r"(r[1]), "=r"(r[2]), "=r"(r[3]) : "r"(a));
}
__device__ __forceinline__ void mma16816(float* c, const uint32_t* a, const uint32_t* b) {
    asm volatile("mma.sync.aligned.m16n8k16.row.col.f32.f16.f16.f32 "
                 "{%0,%1,%2,%3}, {%4,%5,%6,%7}, {%8,%9}, {%0,%1,%2,%3};"
                 : "+f"(c[0]), "+f"(c[1]), "+f"(c[2]), "+f"(c[3])
                 : "r"(a[0]), "r"(a[1]), "r"(a[2]), "r"(a[3]), "r"(b[0]), "r"(b[1]));
}
__device__ __forceinline__ uint32_t pack2(__half a, __half b) {
    return (uint32_t)__half_as_ushort(a) | ((uint32_t)__half_as_ushort(b) << 16);
}
__device__ __forceinline__ float gelu1(float v) {
    return 0.5f * v * (1.f + erff(v * 0.70710678118654752f));
}

// ---- GEMM: C[M,N] = A[M,K] @ W[N,K]^T, fp16 in, fp32 accum ----
#define BM 128
#define BN 256
#define OW  16384
#define STG 49152
#define NSTAGE 4
#define SMEMSZ (NSTAGE * STG)
#define NTHR 512

__device__ __forceinline__ void ld_tile(uint32_t tb, const __half* __restrict__ g,
                                        int row0, int K, int k0, int nrows, int tid) {
    const char* base = (const char*)(g + (size_t)row0 * K + k0);
    const size_t rs = (size_t)K * 2;
    #pragma unroll
    for (int i = tid; i < nrows * 8; i += NTHR) {
        int r = i >> 3, c2 = i & 7;
        uint32_t off = (uint32_t)(r * 128 + c2 * 16);
        uint32_t dst = tb + (off ^ ((off >> 3) & 0x70));
        asm volatile("cp.async.cg.shared.global [%0], [%1], 16;"
                     :: "r"(dst), "l"(base + (size_t)r * rs + c2 * 16));
    }
}
__device__ __forceinline__ void load_stage(uint32_t sb, int s,
    const __half* A, const __half* W, int bm, int bn, int K, int c, int tid) {
    uint32_t st = sb + (uint32_t)s * STG;
    ld_tile(st,      A, bm, K, c * 64, 128, tid);
    ld_tile(st + OW, W, bn, K, c * 64, 256, tid);
    asm volatile("cp.async.commit_group;" ::: "memory");
}

template<int EP>
__global__ void __launch_bounds__(NTHR, 1)
gemm_tc(const __half* __restrict__ A, const __half* __restrict__ W,
        const float* __restrict__ bias, const float* __restrict__ extra,
        float* __restrict__ Cf, __half* __restrict__ Oh,
        int N, int K, size_t zA, size_t zW, size_t zC)
{
    extern __shared__ __align__(1024) char smem[];
    uint32_t sb = smem_u32(smem);
    const int tid = threadIdx.x, lane = tid & 31, wid = tid >> 5;
    const int bm = blockIdx.y * BM, bn = blockIdx.x * BN;
    const size_t z = blockIdx.z;
    A += z * zA; W += z * zW;

    float acc[2][8][4] = {};

    const int wm = (wid & 3) * 32, wn = (wid >> 2) * 64;
    const int arow = (lane & 7) + ((lane >> 3) & 1) * 8;
    const int ac   = (lane >> 4) & 1;
    const uint32_t axor = (uint32_t)((arow & 7) << 4);
    uint32_t aterm[2];
    #pragma unroll
    for (int mt = 0; mt < 2; mt++) aterm[mt] = (uint32_t)((wm + mt * 16 + arow) * 128);

    const int brow = lane & 7;
    const int bk   = (lane >> 3) & 1;
    const int bn8  = (lane >> 4) & 1;
    const uint32_t bxor = (uint32_t)(brow << 4);
    uint32_t bterm[4];
    #pragma unroll
    for (int ntp = 0; ntp < 4; ntp++)
        bterm[ntp] = (uint32_t)((wn + ntp * 16 + bn8 * 8 + brow) * 128);

    const int nch = K >> 6;
    load_stage(sb, 0, A, W, bm, bn, K, 0, tid);
    load_stage(sb, 1, A, W, bm, bn, K, 1, tid);
    load_stage(sb, 2, A, W, bm, bn, K, 2, tid);

    for (int c = 0; c < nch; c++) {
        asm volatile("cp.async.wait_group 2;" ::: "memory");
        __syncthreads();
        if (c + 3 < nch) load_stage(sb, (c + 3) % NSTAGE, A, W, bm, bn, K, c + 3, tid);
        else             asm volatile("cp.async.commit_group;" ::: "memory");

        uint32_t st = sb + (uint32_t)(c % NSTAGE) * STG;
        #pragma unroll
        for (int ks = 0; ks < 4; ks++) {
            const uint32_t ka = (uint32_t)(ks * 32 + ac * 16);
            const uint32_t kb = (uint32_t)(ks * 32 + bk * 16);
            uint32_t fb[8][2];
            #pragma unroll
            for (int ntp = 0; ntp < 4; ntp++)
                ldsm4(&fb[2 * ntp][0], st + OW + bterm[ntp] + (kb ^ bxor));
            #pragma unroll
            for (int mt = 0; mt < 2; mt++) {
                uint32_t fa[4];
                ldsm4(fa, st + aterm[mt] + (ka ^ axor));
                #pragma unroll
                for (int nt = 0; nt < 8; nt++)
                    mma16816(acc[mt][nt], fa, fb[nt]);
            }
        }
    }

    const int r0b = bm + wm + (lane >> 2);
    const int c0b = bn + wn + 2 * (lane & 3);
    #pragma unroll
    for (int mt = 0; mt < 2; mt++) {
        const int row0 = r0b + mt * 16, row1 = row0 + 8;
        #pragma unroll
        for (int nt = 0; nt < 8; nt++) {
            const int col = c0b + nt * 8;
            const float b0 = bias[col], b1 = bias[col + 1];
            float v00 = acc[mt][nt][0] + b0, v01 = acc[mt][nt][1] + b1;
            float v10 = acc[mt][nt][2] + b0, v11 = acc[mt][nt][3] + b1;
            const size_t g0 = z * zC + (size_t)row0 * N + col;
            const size_t g1 = z * zC + (size_t)row1 * N + col;

            if (EP == EP_GELUH) {
                v00 = gelu1(v00); v01 = gelu1(v01); v10 = gelu1(v10); v11 = gelu1(v11);
            }
            if (EP == EP_ADDH) {
                float2 e0 = *(const float2*)(extra + g0);
                float2 e1 = *(const float2*)(extra + g1);
                v00 += e0.x; v01 += e0.y; v10 += e1.x; v11 += e1.y;
            }
            if (EP == EP_GELUH || EP == EP_HALF || EP == EP_ADDH) {
                *(uint32_t*)(Oh + g0) = pack2(__float2half_rn(v00), __float2half_rn(v01));
                *(uint32_t*)(Oh + g1) = pack2(__float2half_rn(v10), __float2half_rn(v11));
            } else {
                *(float2*)(Cf + g0) = make_float2(v00, v01);
                *(float2*)(Cf + g1) = make_float2(v10, v11);
            }
        }
    }
}

// ---- elementwise / small kernels ----
template<int SILU>
__global__ void cvt_k(const float* __restrict__ s, __half* __restrict__ o, int n) {
    int i = (blockIdx.x * blockDim.x + threadIdx.x) * 8;
    if (i >= n) return;
    float4 a = *(const float4*)(s + i);
    float4 b = *(const float4*)(s + i + 4);
    if (SILU) {
        a.x /= (1.f + expf(-a.x)); a.y /= (1.f + expf(-a.y));
        a.z /= (1.f + expf(-a.z)); a.w /= (1.f + expf(-a.w));
        b.x /= (1.f + expf(-b.x)); b.y /= (1.f + expf(-b.y));
        b.z /= (1.f + expf(-b.z)); b.w /= (1.f + expf(-b.w));
    }
    uint4 r;
    r.x = pack2(__float2half_rn(a.x), __float2half_rn(a.y));
    r.y = pack2(__float2half_rn(a.z), __float2half_rn(a.w));
    r.z = pack2(__float2half_rn(b.x), __float2half_rn(b.y));
    r.w = pack2(__float2half_rn(b.z), __float2half_rn(b.w));
    *(uint4*)(o + i) = r;
}

__global__ void transpose_wv(const float* __restrict__ wqkv, __half* __restrict__ wvt) {
    __shared__ float tile[32][65];
    const int l = blockIdx.z;
    const float* src = wqkv + (size_t)l * 3 * D2 + 2 * D2;
    __half* dst = wvt + (size_t)l * D2;
    const int k0 = blockIdx.x * 32, m0 = blockIdx.y * 64;
    const int tx = threadIdx.x, ty = threadIdx.y;
    #pragma unroll
    for (int i = 0; i < 8; i++) {
        int m = ty + i * 8;
        tile[tx][m] = src[(size_t)(m0 + m) * DIM + k0 + tx];
    }
    __syncthreads();
    #pragma unroll
    for (int i = 0; i < 4; i++) {
        int k = ty * 4 + i;
        __half2 v = __floats2half2_rn(tile[k][2 * tx], tile[k][2 * tx + 1]);
        *(__half2*)(dst + (size_t)(k0 + k) * DIM + m0 + 2 * tx) = v;
    }
}

__global__ __launch_bounds__(256) void bprime_k(
    const float* __restrict__ wo, const float* __restrict__ bqkv,
    const float* __restrict__ bo, float* __restrict__ bp)
{
    const int n = blockIdx.x, l = blockIdx.y, t = threadIdx.x;
    const float* wr = wo + (size_t)l * D2 + (size_t)n * DIM;
    const float* bv = bqkv + (size_t)l * 3 * DIM + 2 * DIM;
    float s = 0.f;
    for (int k = t; k < DIM; k += 256) s += wr[k] * bv[k];
    #pragma unroll
    for (int o = 16; o; o >>= 1) s += __shfl_xor_sync(0xffffffffu, s, o);
    __shared__ float ss[8];
    if ((t & 31) == 0) ss[t >> 5] = s;
    __syncthreads();
    if (t == 0) {
        float r = 0.f;
        #pragma unroll
        for (int i = 0; i < 8; i++) r += ss[i];
        bp[l * DIM + n] = r + bo[l * DIM + n];
    }
}

__device__ __forceinline__ void ln_apply(
    float4* v, int row, int lane,
    const float* __restrict__ g, const float* __restrict__ b,
    const __half* __restrict__ ada, int so, int sho, __half* __restrict__ oh)
{
    float s = 0.f, q = 0.f;
    #pragma unroll
    for (int i = 0; i < 8; i++) {
        s += v[i].x + v[i].y + v[i].z + v[i].w;
        q += v[i].x*v[i].x + v[i].y*v[i].y + v[i].z*v[i].z + v[i].w*v[i].w;
    }
    #pragma unroll
    for (int o = 16; o; o >>= 1) {
        s += __shfl_xor_sync(0xffffffffu, s, o);
        q += __shfl_xor_sync(0xffffffffu, q, o);
    }
    const float m   = s * (1.f / DIM);
    const float inv = rsqrtf(q * (1.f / DIM) - m * m + 1e-5f);
    const __half* ar = ada ? ada + (size_t)row * (16 * DIM) : nullptr;
    #pragma unroll
    for (int i = 0; i < 8; i++) {
        const int e = (i * 32 + lane) * 4;
        float4 g4 = ((const float4*)g)[i * 32 + lane];
        float4 b4 = ((const float4*)b)[i * 32 + lane];
        float o0 = (v[i].x - m) * inv * g4.x + b4.x;
        float o1 = (v[i].y - m) * inv * g4.y + b4.y;
        float o2 = (v[i].z - m) * inv * g4.z + b4.z;
        float o3 = (v[i].w - m) * inv * g4.w + b4.w;
        if (ar) {
            __half2 sa = ((const __half2*)(ar + so + e))[0];
            __half2 sb2 = ((const __half2*)(ar + so + e))[1];
            __half2 ha = ((const __half2*)(ar + sho + e))[0];
            __half2 hb = ((const __half2*)(ar + sho + e))[1];
            o0 = o0 * (1.f + __low2float(sa))  + __low2float(ha);
            o1 = o1 * (1.f + __high2float(sa)) + __high2float(ha);
            o2 = o2 * (1.f + __low2float(sb2)) + __low2float(hb);
            o3 = o3 * (1.f + __high2float(sb2))+ __high2float(hb);
        }
        ((uint2*)(oh + (size_t)row * DIM))[i * 32 + lane] =
            make_uint2(pack2(__float2half_rn(o0), __float2half_rn(o1)),
                       pack2(__float2half_rn(o2), __float2half_rn(o3)));
    }
}

// LN only (h fp16, already final)
__global__ __launch_bounds__(256) void ln_half_k(
    const __half* __restrict__ h, const float* __restrict__ g,
    const float* __restrict__ b, const __half* __restrict__ ada,
    int so, int sho, __half* __restrict__ oh)
{
    const int lane = threadIdx.x & 31;
    const int row  = blockIdx.x * 8 + (threadIdx.x >> 5);
    const uint2* hr = (const uint2*)(h + (size_t)row * DIM);
    float4 v[8];
    #pragma unroll
    for (int i = 0; i < 8; i++) {
        uint2 hv = hr[i * 32 + lane];
        __half2 h0 = *(__half2*)&hv.x, h1 = *(__half2*)&hv.y;
        v[i] = make_float4(__low2float(h0), __high2float(h0),
                           __low2float(h1), __high2float(h1));
    }
    ln_apply(v, row, lane, g, b, ada, so, sho, oh);
}

// residual + LN: t = h + y (fp32); LN uses t; store fp16(t) for future layers.
// WH=0 skips the h write-back (final out-LN; h dead after).
template<int WH>
__global__ __launch_bounds__(256) void ln_res_k(
    __half* __restrict__ h, const __half* __restrict__ y,
    const float* __restrict__ g, const float* __restrict__ b,
    const __half* __restrict__ ada, int so, int sho, __half* __restrict__ oh)
{
    const int lane = threadIdx.x & 31;
    const int row  = blockIdx.x * 8 + (threadIdx.x >> 5);
    uint2* hr = (uint2*)(h + (size_t)row * DIM);
    const uint2* yr = (const uint2*)(y + (size_t)row * DIM);
    float4 v[8];
    #pragma unroll
    for (int i = 0; i < 8; i++) {
        uint2 hv = hr[i * 32 + lane];
        uint2 yv = yr[i * 32 + lane];
        __half2 h0 = *(__half2*)&hv.x, h1 = *(__half2*)&hv.y;
        __half2 y0 = *(__half2*)&yv.x, y1 = *(__half2*)&yv.y;
        float t0 = __low2float(h0) + __low2float(y0);
        float t1 = __high2float(h0) + __high2float(y0);
        float t2 = __low2float(h1) + __low2float(y1);
        float t3 = __high2float(h1) + __high2float(y1);
        if (WH)
            hr[i * 32 + lane] = make_uint2(pack2(__float2half_rn(t0), __float2half_rn(t1)),
                                           pack2(__float2half_rn(t2), __float2half_rn(t3)));
        v[i] = make_float4(t0, t1, t2, t3);
    }
    ln_apply(v, row, lane, g, b, ada, so, sho, oh);
}

// ---- launch ----
extern "C" void kernel_launch(void* const* d_in, const int* in_sizes, int n_in,
                              void* d_out, int out_size)
{
    const float* x        = (const float*)d_in[0];
    const float* t_emb    = (const float*)d_in[1];
    const float* condition= (const float*)d_in[2];
    const float* in_w     = (const float*)d_in[3];
    const float* in_b     = (const float*)d_in[4];
    const float* ln1_g    = (const float*)d_in[5];
    const float* ln1_b    = (const float*)d_in[6];
    const float* wqkv     = (const float*)d_in[7];
    const float* bqkv     = (const float*)d_in[8];
    const float* wo       = (const float*)d_in[9];
    const float* bo       = (const float*)d_in[10];
    const float* ln2_g    = (const float*)d_in[11];
    const float* ln2_b    = (const float*)d_in[12];
    const float* w1       = (const float*)d_in[13];
    const float* b1       = (const float*)d_in[14];
    const float* w2       = (const float*)d_in[15];
    const float* b2       = (const float*)d_in[16];
    const float* ada_w    = (const float*)d_in[17];
    const float* ada_b    = (const float*)d_in[18];
    const float* out_ln_g = (const float*)d_in[19];
    const float* out_ln_b = (const float*)d_in[20];
    const float* out_w    = (const float*)d_in[21];
    const float* out_b    = (const float*)d_in[22];

    float *bp, *zero;
    __half *h,*adah,*xh,*y,*st,*big,*w,*woh,*wvt,*wp;
    cudaGetSymbolAddress((void**)&h,    g_h);
    cudaGetSymbolAddress((void**)&bp,   g_bp);
    cudaGetSymbolAddress((void**)&zero, g_zero);
    cudaGetSymbolAddress((void**)&adah, g_adah);
    cudaGetSymbolAddress((void**)&xh,   g_xh);
    cudaGetSymbolAddress((void**)&y,    g_y);
    cudaGetSymbolAddress((void**)&st,   g_st);
    cudaGetSymbolAddress((void**)&big,  g_big);
    cudaGetSymbolAddress((void**)&w,    g_w);
    cudaGetSymbolAddress((void**)&woh,  g_woh);
    cudaGetSymbolAddress((void**)&wvt,  g_wvt);
    cudaGetSymbolAddress((void**)&wp,   g_wp);

    cudaFuncSetAttribute(gemm_tc<EP_BIAS>,  cudaFuncAttributeMaxDynamicSharedMemorySize, SMEMSZ);
    cudaFuncSetAttribute(gemm_tc<EP_ADDH>,  cudaFuncAttributeMaxDynamicSharedMemorySize, SMEMSZ);
    cudaFuncSetAttribute(gemm_tc<EP_GELUH>, cudaFuncAttributeMaxDynamicSharedMemorySize, SMEMSZ);
    cudaFuncSetAttribute(gemm_tc<EP_HALF>,  cudaFuncAttributeMaxDynamicSharedMemorySize, SMEMSZ);

    const size_t OFF_ADA = D2, OFF_W1 = 5 * D2, OFF_W2 = 21 * D2, OFF_OUT = 37 * D2;

    const int sb = 256;
    auto cvtS = [&](cudaStream_t sN, const float* src, __half* o, size_t n) {
        cvt_k<0><<<(int)((n / 8 + sb - 1) / sb), sb, 0, sN>>>(src, o, (int)n);
    };

    const dim3 blk(NTHR);
    const dim3 gD  (DIM / BN, BATCH / BM);
    const dim3 g4D (4 * DIM / BN, BATCH / BM);
    const dim3 gAda(16 * DIM / BN, BATCH / BM);
    const dim3 gWp (DIM / BN, DIM / BM, NL);

    // fork (R13 layout): big weight cvts on side stream
    cudaStream_t s2;
    cudaStreamCreateWithFlags(&s2, cudaStreamNonBlocking);
    cudaEvent_t eF, eJ;
    cudaEventCreateWithFlags(&eF, cudaEventDisableTiming);
    cudaEventCreateWithFlags(&eJ, cudaEventDisableTiming);
    cudaEventRecord(eF, 0);
    cudaStreamWaitEvent(s2, eF, 0);
    cvtS(s2, w1,    w + OFF_W1,  16 * D2);
    cvtS(s2, w2,    w + OFF_W2,  16 * D2);
    cvtS(s2, out_w, w + OFF_OUT, D2);
    cudaEventRecord(eJ, s2);

    cvtS(0, x, xh, (size_t)BATCH * DIM);
    cvt_k<1><<<(BATCH * TEMB / 8 + sb - 1) / sb, sb>>>(t_emb, st, BATCH * TEMB);
    cvtS(0, in_w,  w,           D2);
    cvtS(0, ada_w, w + OFF_ADA, 4 * D2);
    cvtS(0, wo,    woh,         4 * D2);
    transpose_wv<<<dim3(DIM / 32, DIM / 64, NL), dim3(32, 8)>>>(wqkv, wvt);
    bprime_k<<<dim3(DIM, NL), 256>>>(wo, bqkv, bo, bp);

    gemm_tc<EP_HALF><<<gWp, blk, SMEMSZ>>>(woh, wvt, zero, nullptr, nullptr, wp,
                                           DIM, DIM, D2, D2, D2);
    gemm_tc<EP_HALF><<<gAda, blk, SMEMSZ>>>(st, w + OFF_ADA, ada_b, nullptr, nullptr, adah,
                                            16 * DIM, TEMB, 0, 0, 0);
    // h = fp16(x @ in_w^T + in_b + condition)
    gemm_tc<EP_ADDH><<<gD, blk, SMEMSZ>>>(xh, w, in_b, condition, nullptr, h,
                                          DIM, DIM, 0, 0, 0);
    ln_half_k<<<BATCH / 8, 256>>>(h, ln1_g, ln1_b, adah, 0, DIM, xh);

    cudaStreamWaitEvent(0, eJ, 0);

    for (int l = 0; l < NL; l++) {
        const int ao = l * 4 * DIM;
        gemm_tc<EP_HALF><<<gD, blk, SMEMSZ>>>(xh, wp + (size_t)l * D2,
                                              bp + (size_t)l * DIM, nullptr, nullptr, y,
                                              DIM, DIM, 0, 0, 0);
        ln_res_k<1><<<BATCH / 8, 256>>>(h, y, ln2_g + (size_t)l * DIM, ln2_b + (size_t)l * DIM,
                                        adah, ao + 2 * DIM, ao + 3 * DIM, xh);
        gemm_tc<EP_GELUH><<<g4D, blk, SMEMSZ>>>(xh, w + OFF_W1 + (size_t)l * 4 * D2,
                                                b1 + (size_t)l * 4 * DIM, nullptr, nullptr, big,
                                                4 * DIM, DIM, 0, 0, 0);
        gemm_tc<EP_HALF><<<gD, blk, SMEMSZ>>>(big, w + OFF_W2 + (size_t)l * 4 * D2,
                                              b2 + (size_t)l * DIM, nullptr, nullptr, y,
                                              DIM, 4 * DIM, 0, 0, 0);
        if (l < NL - 1) {
            const int ao2 = (l + 1) * 4 * DIM;
            ln_res_k<1><<<BATCH / 8, 256>>>(h, y, ln1_g + (size_t)(l + 1) * DIM,
                                            ln1_b + (size_t)(l + 1) * DIM,
                                            adah, ao2, ao2 + DIM, xh);
        } else {
            ln_res_k<0><<<BATCH / 8, 256>>>(h, y, out_ln_g, out_ln_b, nullptr, 0, 0, xh);
        }
    }

    gemm_tc<EP_BIAS><<<gD, blk, SMEMSZ>>>(xh, w + OFF_OUT, out_b, nullptr,
                                          (float*)d_out, nullptr, DIM, DIM, 0, 0, 0);
}